// round 8
// baseline (speedup 1.0000x reference)
#include <cuda_runtime.h>
#include <cuda_fp16.h>
#include <cstdint>

// ---------------------------------------------------------------------------
// GCN-VAE encoder. Round 8:
//  - warp-per-node gather (no intra-warp divergence, 8-edge unroll)
//  - single-kernel CSR build with co-resident grid barriers
//  - HMMA GEMMs + prescaled fp16 features (unchanged from round 7 champion)
// ---------------------------------------------------------------------------

#define N_NODES 100000
#define E_MAX   1700000

__device__ int    g_sync;
__device__ int    g_cnt   [N_NODES];
__device__ int    g_off   [N_NODES + 1];
__device__ int    g_cursor[N_NODES];
__device__ int    g_bsum  [128];
__device__ int    g_csr   [E_MAX];
__device__ float  g_dinv  [N_NODES];
__device__ __half g_xh  [(size_t)N_NODES * 64];      // fp16 dinv*x
__device__ __half g_aggH[(size_t)N_NODES * 128];     // fp16 aggregated features
__device__ __half g_bufH[(size_t)N_NODES * 128];     // fp16 dinv*hidden
__device__ __half g_wh1 [64  * 128];
__device__ __half g_wh2 [128 * 128];
__device__ __half g_whh [128 * 128];                 // [Wmu | Wlv]

// ------------------------------- setup --------------------------------------

__global__ void k_setup(int* __restrict__ cnt, int M,
                        const float* __restrict__ W1, const float* __restrict__ W2,
                        const float* __restrict__ Wmu, const float* __restrict__ Wlv,
                        __half* __restrict__ Wh1, __half* __restrict__ Wh2,
                        __half* __restrict__ Whh) {
    int i = blockIdx.x * blockDim.x + threadIdx.x;
    if (i == 0) g_sync = 0;
    if (i < M) cnt[i] = 0;
    if (i < 64 * 128) Wh1[i] = __float2half_rn(W1[i]);
    if (i < 128 * 128) {
        Wh2[i] = __float2half_rn(W2[i]);
        int k = i >> 7, j = i & 127;
        Whh[i] = __float2half_rn(j < 64 ? Wmu[k * 64 + j] : Wlv[k * 64 + (j - 64)]);
    }
}

// --------------------- single-kernel CSR build -------------------------------
// 128 blocks, all co-resident (<=148 SMs) -> atomic-counter grid barrier safe.

__device__ __forceinline__ void gbar(int target) {
    __syncthreads();
    if (threadIdx.x == 0) {
        __threadfence();
        atomicAdd(&g_sync, 1);
        while (atomicAdd(&g_sync, 0) < target) { }
    }
    __syncthreads();
}

__global__ void __launch_bounds__(256)
k_csr(const int* __restrict__ src, const int* __restrict__ dst,
      int* __restrict__ cnt, int* __restrict__ off, int* __restrict__ cursor,
      int* __restrict__ bsum, int* __restrict__ csr, float* __restrict__ dinv,
      int M, int E) {
    const int tid = threadIdx.x;
    const int bid = blockIdx.x;
    const int NB = gridDim.x;                  // 128
    const int nscan = (M + 1023) >> 10;        // 98

    // phase 1: degree histogram
    for (int i = bid * 256 + tid; i < E; i += NB * 256)
        atomicAdd(&cnt[dst[i]], 1);
    gbar(NB);

    // phase 2a: block-local scan (1024 elems per block, blocks < nscan)
    __shared__ int s[256];
    int v[4], run = 0;
    const int base = bid * 1024 + tid * 4;
    if (bid < nscan) {
        int tsum = 0;
#pragma unroll
        for (int r = 0; r < 4; r++) {
            int idx = base + r;
            v[r] = (idx < M) ? cnt[idx] : 0;
            tsum += v[r];
        }
        s[tid] = tsum;
        __syncthreads();
        for (int d = 1; d < 256; d <<= 1) {
            int add = (tid >= d) ? s[tid - d] : 0;
            __syncthreads();
            s[tid] += add;
            __syncthreads();
        }
        run = s[tid] - tsum;
        if (tid == 255) bsum[bid] = s[255];
    }
    gbar(2 * NB);

    // phase 2b: block 0 exclusive-scans the partials
    if (bid == 0) {
        int val = (tid < nscan) ? bsum[tid] : 0;
        s[tid] = val;
        __syncthreads();
        for (int d = 1; d < 256; d <<= 1) {
            int add = (tid >= d) ? s[tid - d] : 0;
            __syncthreads();
            s[tid] += add;
            __syncthreads();
        }
        if (tid < nscan) bsum[tid] = s[tid] - val;
    }
    gbar(3 * NB);

    // phase 2c: write off / cursor / dinv
    if (bid < nscan) {
        int o = run + bsum[bid];
#pragma unroll
        for (int r = 0; r < 4; r++) {
            int idx = base + r;
            if (idx < M) {
                off[idx] = o;
                cursor[idx] = o;
                dinv[idx] = rsqrtf((float)(v[r] + 1));
                o += v[r];
            }
        }
    }
    if (bid == 0 && tid == 0) off[M] = E;
    gbar(4 * NB);

    // phase 3: CSR fill
    for (int i = bid * 256 + tid; i < E; i += NB * 256) {
        int pos = atomicAdd(&cursor[dst[i]], 1);
        csr[pos] = src[i];
    }
}

// ----------------------- x -> fp16(dinv * x) --------------------------------

__global__ void k_cvt(const float* __restrict__ in, const float* __restrict__ dinv,
                      __half* __restrict__ outp, int M) {
    int i = blockIdx.x * blockDim.x + threadIdx.x;   // one uint4 (8 halves)
    if (i >= M * 8) return;
    int row = i >> 3;
    float w = dinv[row];
    float4 a = reinterpret_cast<const float4*>(in)[2 * i];
    float4 b = reinterpret_cast<const float4*>(in)[2 * i + 1];
    __half2 h[4];
    h[0] = __float22half2_rn(make_float2(w * a.x, w * a.y));
    h[1] = __float22half2_rn(make_float2(w * a.z, w * a.w));
    h[2] = __float22half2_rn(make_float2(w * b.x, w * b.y));
    h[3] = __float22half2_rn(make_float2(w * b.z, w * b.w));
    reinterpret_cast<uint4*>(outp)[i] = *reinterpret_cast<uint4*>(h);
}

// ----------------------- warp-per-node gather -------------------------------
// agg = fp16( dinv_i * ( t'[i] + sum_j t'[j] ) ),  t' = dinv*t, fp32 accum.
// One warp per node; lane owns D/32 halves. 8-edge unroll, no divergence.

template <int D>
__global__ void __launch_bounds__(256)
k_gather_w(__half* __restrict__ acc, const __half* __restrict__ t,
           const int* __restrict__ csr, const int* __restrict__ off,
           const float* __restrict__ dinv, int n) {
    constexpr int EL = D / 32;                 // halves per lane: 4 / 2
    int gid  = (blockIdx.x * 256 + threadIdx.x) >> 5;
    int lane = threadIdx.x & 31;
    if (gid >= n) return;
    const __half* tl = t + (size_t)lane * EL;

    float a[EL];
    // self term
    if constexpr (EL == 4) {
        uint2 u = *reinterpret_cast<const uint2*>(tl + (size_t)gid * D);
        float2 f0 = __half22float2(*reinterpret_cast<__half2*>(&u.x));
        float2 f1 = __half22float2(*reinterpret_cast<__half2*>(&u.y));
        a[0] = f0.x; a[1] = f0.y; a[2] = f1.x; a[3] = f1.y;
    } else {
        unsigned u = *reinterpret_cast<const unsigned*>(tl + (size_t)gid * D);
        float2 f0 = __half22float2(*reinterpret_cast<__half2*>(&u));
        a[0] = f0.x; a[1] = f0.y;
    }

    int e   = off[gid];
    int end = off[gid + 1];
    for (; e + 8 <= end; e += 8) {
        int sidx[8];
#pragma unroll
        for (int q = 0; q < 8; q++) sidx[q] = csr[e + q];
        if constexpr (EL == 4) {
            uint2 u[8];
#pragma unroll
            for (int q = 0; q < 8; q++)
                u[q] = *reinterpret_cast<const uint2*>(tl + (size_t)sidx[q] * D);
#pragma unroll
            for (int q = 0; q < 8; q++) {
                float2 f0 = __half22float2(*reinterpret_cast<__half2*>(&u[q].x));
                float2 f1 = __half22float2(*reinterpret_cast<__half2*>(&u[q].y));
                a[0] += f0.x; a[1] += f0.y; a[2] += f1.x; a[3] += f1.y;
            }
        } else {
            unsigned u[8];
#pragma unroll
            for (int q = 0; q < 8; q++)
                u[q] = *reinterpret_cast<const unsigned*>(tl + (size_t)sidx[q] * D);
#pragma unroll
            for (int q = 0; q < 8; q++) {
                float2 f0 = __half22float2(*reinterpret_cast<__half2*>(&u[q]));
                a[0] += f0.x; a[1] += f0.y;
            }
        }
    }
    for (; e < end; e++) {
        int s0 = csr[e];
        if constexpr (EL == 4) {
            uint2 u = *reinterpret_cast<const uint2*>(tl + (size_t)s0 * D);
            float2 f0 = __half22float2(*reinterpret_cast<__half2*>(&u.x));
            float2 f1 = __half22float2(*reinterpret_cast<__half2*>(&u.y));
            a[0] += f0.x; a[1] += f0.y; a[2] += f1.x; a[3] += f1.y;
        } else {
            unsigned u = *reinterpret_cast<const unsigned*>(tl + (size_t)s0 * D);
            float2 f0 = __half22float2(*reinterpret_cast<__half2*>(&u));
            a[0] += f0.x; a[1] += f0.y;
        }
    }

    float w = dinv[gid];
    if constexpr (EL == 4) {
        __half2 h0 = __floats2half2_rn(w * a[0], w * a[1]);
        __half2 h1 = __floats2half2_rn(w * a[2], w * a[3]);
        uint2 o;
        o.x = *reinterpret_cast<unsigned*>(&h0);
        o.y = *reinterpret_cast<unsigned*>(&h1);
        *reinterpret_cast<uint2*>(acc + (size_t)gid * D + lane * EL) = o;
    } else {
        __half2 h0 = __floats2half2_rn(w * a[0], w * a[1]);
        *reinterpret_cast<unsigned*>(acc + (size_t)gid * D + lane * EL) =
            *reinterpret_cast<unsigned*>(&h0);
    }
}

// ------------------------------- HMMA GEMM ----------------------------------

template <int K, bool RELU, bool SPLIT>
__global__ void __launch_bounds__(256)
k_hgemm(const __half* __restrict__ A, const __half* __restrict__ Wh,
        const float* __restrict__ b0, const float* __restrict__ b1,
        const float* __restrict__ dinv,
        __half* __restrict__ H, float* __restrict__ C0, float* __restrict__ C1,
        int M) {
    __shared__ __half Xs[128][72];
    __shared__ __half Ws[64][136];

    const int tid = threadIdx.x;
    const int wid = tid >> 5;
    const int lane = tid & 31;
    const int mg = wid >> 1;
    const int ng = wid & 1;
    const int row0 = blockIdx.x * 128;

    float acc[2][8][4];
#pragma unroll
    for (int mt = 0; mt < 2; mt++)
#pragma unroll
        for (int nt = 0; nt < 8; nt++)
#pragma unroll
            for (int q = 0; q < 4; q++) acc[mt][nt][q] = 0.f;

    for (int kc = 0; kc < K; kc += 64) {
#pragma unroll
        for (int i = tid; i < 128 * 8; i += 256) {
            int r = i >> 3, c8 = i & 7;
            int grow = row0 + r;
            uint4 v = make_uint4(0u, 0u, 0u, 0u);
            if (grow < M)
                v = *reinterpret_cast<const uint4*>(A + (size_t)grow * K + kc + c8 * 8);
            *reinterpret_cast<uint4*>(&Xs[r][c8 * 8]) = v;
        }
#pragma unroll
        for (int i = tid; i < 64 * 16; i += 256) {
            int k = i >> 4, n8 = i & 15;
            uint4 v = *reinterpret_cast<const uint4*>(Wh + (size_t)(kc + k) * 128 + n8 * 8);
            *reinterpret_cast<uint4*>(&Ws[k][n8 * 8]) = v;
        }
        __syncthreads();

#pragma unroll
        for (int ks = 0; ks < 4; ks++) {
            uint32_t af[2][4];
#pragma unroll
            for (int mt = 0; mt < 2; mt++) {
                int r = mg * 32 + mt * 16 + (lane & 15);
                int c = ks * 16 + (lane >> 4) * 8;
                uint32_t addr = (uint32_t)__cvta_generic_to_shared(&Xs[r][c]);
                asm volatile(
                    "ldmatrix.sync.aligned.m8n8.x4.shared.b16 {%0,%1,%2,%3}, [%4];"
                    : "=r"(af[mt][0]), "=r"(af[mt][1]), "=r"(af[mt][2]), "=r"(af[mt][3])
                    : "r"(addr));
            }
#pragma unroll
            for (int nt = 0; nt < 8; nt++) {
                int k = ks * 16 + (lane & 15);
                int c = ng * 64 + nt * 8;
                uint32_t addr = (uint32_t)__cvta_generic_to_shared(&Ws[k][c]);
                uint32_t bf0, bf1;
                asm volatile(
                    "ldmatrix.sync.aligned.m8n8.x2.trans.shared.b16 {%0,%1}, [%2];"
                    : "=r"(bf0), "=r"(bf1) : "r"(addr));
#pragma unroll
                for (int mt = 0; mt < 2; mt++) {
                    asm volatile(
                        "mma.sync.aligned.m16n8k16.row.col.f32.f16.f16.f32 "
                        "{%0,%1,%2,%3}, {%4,%5,%6,%7}, {%8,%9}, {%0,%1,%2,%3};"
                        : "+f"(acc[mt][nt][0]), "+f"(acc[mt][nt][1]),
                          "+f"(acc[mt][nt][2]), "+f"(acc[mt][nt][3])
                        : "r"(af[mt][0]), "r"(af[mt][1]), "r"(af[mt][2]), "r"(af[mt][3]),
                          "r"(bf0), "r"(bf1));
                }
            }
        }
        __syncthreads();
    }

    const int tig = lane & 3;
    const int grp = lane >> 2;
#pragma unroll
    for (int mt = 0; mt < 2; mt++) {
#pragma unroll
        for (int nt = 0; nt < 8; nt++) {
            int c = ng * 64 + nt * 8 + tig * 2;
#pragma unroll
            for (int hf = 0; hf < 2; hf++) {
                int r = row0 + mg * 32 + mt * 16 + grp + hf * 8;
                if (r >= M) continue;
                float v0 = acc[mt][nt][hf * 2 + 0];
                float v1 = acc[mt][nt][hf * 2 + 1];
                if (!SPLIT) {
                    v0 += b0[c]; v1 += b0[c + 1];
                    if (RELU) { v0 = fmaxf(v0, 0.f); v1 = fmaxf(v1, 0.f); }
                    float dv = dinv[r];
                    *reinterpret_cast<__half2*>(H + (size_t)r * 128 + c) =
                        __floats2half2_rn(v0 * dv, v1 * dv);
                } else if (c < 64) {
                    v0 += b0[c]; v1 += b0[c + 1];
                    *reinterpret_cast<float2*>(C0 + (size_t)r * 64 + c) =
                        make_float2(v0, v1);
                } else {
                    v0 += b1[c - 64]; v1 += b1[c - 63];
                    *reinterpret_cast<float2*>(C1 + (size_t)r * 64 + (c - 64)) =
                        make_float2(v0, v1);
                }
            }
        }
    }
}

// ------------------------------- launcher ----------------------------------

extern "C" void kernel_launch(void* const* d_in, const int* in_sizes, int n_in,
                              void* d_out, int out_size) {
    const float* x   = (const float*)d_in[0];
    const int*   ei  = (const int*)  d_in[1];
    const float* W1  = (const float*)d_in[2];
    const float* b1  = (const float*)d_in[3];
    const float* W2  = (const float*)d_in[4];
    const float* b2  = (const float*)d_in[5];
    const float* Wmu = (const float*)d_in[6];
    const float* bmu = (const float*)d_in[7];
    const float* Wlv = (const float*)d_in[8];
    const float* blv = (const float*)d_in[9];
    float* out = (float*)d_out;

    const int M = in_sizes[0] / 64;
    const int E = in_sizes[1] / 2;
    const int* src = ei;
    const int* dst = ei + E;

    int *cnt, *off, *cursor, *bsum, *csr;
    float *dinv;
    __half *xh, *aggH, *bufH, *wh1, *wh2, *whh;
    cudaGetSymbolAddress((void**)&cnt,    g_cnt);
    cudaGetSymbolAddress((void**)&off,    g_off);
    cudaGetSymbolAddress((void**)&cursor, g_cursor);
    cudaGetSymbolAddress((void**)&bsum,   g_bsum);
    cudaGetSymbolAddress((void**)&csr,    g_csr);
    cudaGetSymbolAddress((void**)&dinv,   g_dinv);
    cudaGetSymbolAddress((void**)&xh,     g_xh);
    cudaGetSymbolAddress((void**)&aggH,   g_aggH);
    cudaGetSymbolAddress((void**)&bufH,   g_bufH);
    cudaGetSymbolAddress((void**)&wh1,    g_wh1);
    cudaGetSymbolAddress((void**)&wh2,    g_wh2);
    cudaGetSymbolAddress((void**)&whh,    g_whh);

    const int T = 256;
    auto nb = [](long n, int t) { return (int)((n + t - 1) / t); };
    const int gB = nb(M, 128);
    const int gW = nb((long)M * 32, T);    // warp-per-node gather grid

    // setup (weights fp16, zero cnt + g_sync) -> single-kernel CSR build -> x'
    k_setup<<<nb(M, T), T>>>(cnt, M, W1, W2, Wmu, Wlv, wh1, wh2, whh);
    k_csr  <<<128, 256>>>(src, dst, cnt, off, cursor, bsum, csr, dinv, M, E);
    k_cvt  <<<nb((long)M * 8, T), T>>>(x, dinv, xh, M);

    // layer 1: gather xh (64) -> HMMA 64->128 relu -> h1' fp16 (prescaled)
    k_gather_w<64><<<gW, T>>>(aggH, xh, csr, off, dinv, M);
    k_hgemm<64, true, false><<<gB, 256>>>(aggH, wh1, b1, nullptr, dinv,
                                          bufH, nullptr, nullptr, M);

    // layer 2: gather h1' (128) -> HMMA 128->128 relu -> h2' fp16 (prescaled)
    k_gather_w<128><<<gW, T>>>(aggH, bufH, csr, off, dinv, M);
    k_hgemm<128, true, false><<<gB, 256>>>(aggH, wh2, b2, nullptr, dinv,
                                           bufH, nullptr, nullptr, M);

    // heads: gather h2' (128) once -> fused mu|logvar HMMA (fp32 split out)
    k_gather_w<128><<<gW, T>>>(aggH, bufH, csr, off, dinv, M);
    k_hgemm<128, false, true><<<gB, 256>>>(aggH, whh, bmu, blv, dinv,
                                           nullptr, out, out + (size_t)M * 64, M);
}